// round 5
// baseline (speedup 1.0000x reference)
#include <cuda_runtime.h>
#include <cuda_fp16.h>
#include <float.h>
#include <stdint.h>

// loss = mean_i [ logsumexp_j t(i,j) - t(i,i) ],  t(i,j) = x_i.y_j - 0.5|y_j|^2
// K=8192, D=128. int8 mma.sync m16n8k32 (s32 exact accum), log2-domain online
// logsumexp, persistent 148-CTA grid. Diagonal exact in fp32.

#define DD      128
#define KTOT    8192
#define BM      128
#define TN      128
#define SROW    144                // bytes per smem row (128 s8 + 16 pad)
#define XTB     (128 * SROW)       // 18432
#define NUNITS  1024               // (8192/128 rb) * (8192/512 cc)
#define NCTA    148
#define LOG2E   1.4426950408889634f
#define LN2     0.6931471805599453f
#define QS      23.0f              // int8 quant scale (127/5.5)
#define SFAC    (LOG2E / (QS * QS))

__device__ int8_t g_xq[KTOT * DD];
__device__ int8_t g_yq[KTOT * DD];
__device__ float  g_ysq[KTOT];          // 0.5*log2e*|y|^2 (exact fp32)
__device__ float  g_diag[KTOT];         // exact t(i,i), natural units
__device__ float  g_m[NUNITS * BM];
__device__ float  g_s[NUNITS * BM];
__device__ float  g_partial[32];
__device__ unsigned g_done;

// ---------------------------------------------------------------------------
__device__ __forceinline__ uint32_t s2u(const void* p) {
    uint32_t a;
    asm("{ .reg .u64 t; cvta.to.shared.u64 t, %1; cvt.u32.u64 %0, t; }"
        : "=r"(a) : "l"(p));
    return a;
}
__device__ __forceinline__ void cp16(uint32_t dst, const void* src) {
    asm volatile("cp.async.cg.shared.global [%0], [%1], 16;"
                 :: "r"(dst), "l"(src) : "memory");
}
__device__ __forceinline__ void ldsm4(uint32_t& r0, uint32_t& r1,
                                      uint32_t& r2, uint32_t& r3, uint32_t a) {
    asm volatile("ldmatrix.sync.aligned.m8n8.x4.shared.b16 {%0,%1,%2,%3}, [%4];"
                 : "=r"(r0), "=r"(r1), "=r"(r2), "=r"(r3) : "r"(a));
}
__device__ __forceinline__ void mma_s8(int* d, const uint32_t* a,
                                       uint32_t b0, uint32_t b1) {
    asm volatile(
        "mma.sync.aligned.m16n8k32.row.col.s32.s8.s8.s32 "
        "{%0,%1,%2,%3}, {%4,%5,%6,%7}, {%8,%9}, {%0,%1,%2,%3};"
        : "+r"(d[0]), "+r"(d[1]), "+r"(d[2]), "+r"(d[3])
        : "r"(a[0]), "r"(a[1]), "r"(a[2]), "r"(a[3]), "r"(b0), "r"(b1));
}
__device__ __forceinline__ float ex2(float x) {
    float r;
    asm("ex2.approx.ftz.f32 %0, %1;" : "=f"(r) : "f"(x));
    return r;
}
__device__ __forceinline__ float lg2(float x) {
    float r;
    asm("lg2.approx.ftz.f32 %0, %1;" : "=f"(r) : "f"(x));
    return r;
}
__device__ __forceinline__ int q8(float v) {
    return __float2int_rn(fminf(fmaxf(v * QS, -127.f), 127.f));
}

// ---------------------------------------------------------------------------
// Prep: int8 quantization + scaled ysq + exact fp32 diagonal. Warp per row.
// ---------------------------------------------------------------------------
__global__ void prep_kernel(const float* __restrict__ X, const float* __restrict__ Y) {
    if (blockIdx.x == 0 && threadIdx.x == 0) g_done = 0u;
    int gw   = (blockIdx.x * blockDim.x + threadIdx.x) >> 5;
    int lane = threadIdx.x & 31;
    if (gw >= KTOT) return;
    float4 xv = ((const float4*)(X + (size_t)gw * DD))[lane];
    float4 yv = ((const float4*)(Y + (size_t)gw * DD))[lane];
    float dot = xv.x * yv.x + xv.y * yv.y + xv.z * yv.z + xv.w * yv.w;
    float ysq = yv.x * yv.x + yv.y * yv.y + yv.z * yv.z + yv.w * yv.w;
    #pragma unroll
    for (int off = 16; off; off >>= 1) {
        dot += __shfl_xor_sync(0xffffffffu, dot, off);
        ysq += __shfl_xor_sync(0xffffffffu, ysq, off);
    }
    uint32_t xp = (uint32_t)(q8(xv.x) & 255) | ((uint32_t)(q8(xv.y) & 255) << 8)
                | ((uint32_t)(q8(xv.z) & 255) << 16) | ((uint32_t)(q8(xv.w) & 255) << 24);
    uint32_t yp = (uint32_t)(q8(yv.x) & 255) | ((uint32_t)(q8(yv.y) & 255) << 8)
                | ((uint32_t)(q8(yv.z) & 255) << 16) | ((uint32_t)(q8(yv.w) & 255) << 24);
    ((uint32_t*)(g_xq + (size_t)gw * DD))[lane] = xp;
    ((uint32_t*)(g_yq + (size_t)gw * DD))[lane] = yp;
    if (lane == 0) {
        g_ysq[gw]  = 0.5f * LOG2E * ysq;
        g_diag[gw] = dot - 0.5f * ysq;
    }
}

// ---------------------------------------------------------------------------
// Main: persistent CTAs, s8 IMMA + fused online logsumexp (log2 domain).
// 256 threads = 8 warps in 4(m) x 2(n); warp tile 32x64.
// Global tile g in [0,4096): rb = g>>6, col = (g&63)*128, unit = g>>2.
// ---------------------------------------------------------------------------
__global__ __launch_bounds__(256)
void infonce_mma_kernel() {
    extern __shared__ char dsm[];
    __shared__ float mh[2][BM], sh[2][BM];

    const int tid  = threadIdx.x;
    const int wid  = tid >> 5;
    const int lane = tid & 31;

    const uint32_t base = s2u(dsm);
    const uint32_t xsb[2] = {base, base + XTB};
    const uint32_t ysb[2] = {base + 2u * XTB, base + 3u * XTB};
    const uint32_t yqb[2] = {base + 4u * XTB, base + 4u * XTB + 512u};

    const int u0 = (blockIdx.x * NUNITS) / NCTA;
    const int u1 = ((blockIdx.x + 1) * NUNITS) / NCTA;
    const int gbeg = u0 * 4, gend = u1 * 4;

    const int mo = (wid >> 1) * 32;
    const int no = (wid & 1) * 64;
    const uint32_t arow = (uint32_t)(mo + (lane & 15));
    const uint32_t acol = (uint32_t)(lane >> 4) * 16u;
    const uint32_t brow = (uint32_t)(no + ((lane >> 4) & 1) * 8 + (lane & 7));
    const uint32_t bkof = (uint32_t)((lane >> 3) & 1) * 16u;
    const int tg = lane & 3;

    // ---- prologue: X(rb0) + Y(gbeg) + ysq(gbeg) ----
    {
        const int rb0 = gbeg >> 6, col = (gbeg & 63) * TN;
        const int8_t* xg = g_xq + (size_t)rb0 * BM * DD;
        const int8_t* yg = g_yq + (size_t)col * DD;
        #pragma unroll
        for (int i = 0; i < 4; i++) {
            int c = i * 256 + tid;
            int r = c >> 3, kc = c & 7;
            cp16(xsb[0] + r * SROW + kc * 16, xg + r * DD + kc * 16);
            cp16(ysb[gbeg & 1] + r * SROW + kc * 16, yg + r * DD + kc * 16);
        }
        if (tid < 32) cp16(yqb[gbeg & 1] + tid * 16, g_ysq + col + tid * 4);
        asm volatile("cp.async.commit_group;" ::: "memory");
    }

    uint32_t afrag[2][4][4];
    int rb_prev = -1, xb = 0;
    float m_run[4], s_run[4];
    #pragma unroll
    for (int i = 0; i < 4; i++) { m_run[i] = -FLT_MAX; s_run[i] = 0.f; }

    #pragma unroll 1
    for (int g = gbeg; g < gend; g++) {
        const int rb = g >> 6;

        // ---- prefetch g+1 ----
        if (g + 1 < gend) {
            const int g2 = g + 1, col2 = (g2 & 63) * TN, rb2 = g2 >> 6;
            const int8_t* yg = g_yq + (size_t)col2 * DD;
            #pragma unroll
            for (int i = 0; i < 4; i++) {
                int c = i * 256 + tid;
                int r = c >> 3, kc = c & 7;
                cp16(ysb[g2 & 1] + r * SROW + kc * 16, yg + r * DD + kc * 16);
            }
            if (tid < 32) cp16(yqb[g2 & 1] + tid * 16, g_ysq + col2 + tid * 4);
            if (rb2 != rb) {
                const int8_t* xg = g_xq + (size_t)rb2 * BM * DD;
                #pragma unroll
                for (int i = 0; i < 4; i++) {
                    int c = i * 256 + tid;
                    int r = c >> 3, kc = c & 7;
                    cp16(xsb[xb ^ 1] + r * SROW + kc * 16, xg + r * DD + kc * 16);
                }
            }
            asm volatile("cp.async.commit_group;" ::: "memory");
            asm volatile("cp.async.wait_group 1;" ::: "memory");
        } else {
            asm volatile("cp.async.wait_group 0;" ::: "memory");
        }
        __syncthreads();

        // ---- (re)load A fragments on row-block change ----
        if (rb != rb_prev) {
            if (rb_prev >= 0) xb ^= 1;
            #pragma unroll
            for (int mt = 0; mt < 2; mt++)
                #pragma unroll
                for (int kt = 0; kt < 4; kt++)
                    ldsm4(afrag[mt][kt][0], afrag[mt][kt][1],
                          afrag[mt][kt][2], afrag[mt][kt][3],
                          xsb[xb] + (arow + mt * 16u) * SROW + kt * 32u + acol);
            rb_prev = rb;
        }

        // ---- GEMM tile (s32 accum, exact) ----
        const uint32_t yb = ysb[g & 1];
        int acc[2][8][4];
        #pragma unroll
        for (int mt = 0; mt < 2; mt++)
            #pragma unroll
            for (int nt = 0; nt < 8; nt++)
                #pragma unroll
                for (int q = 0; q < 4; q++) acc[mt][nt][q] = 0;

        #pragma unroll
        for (int kt = 0; kt < 4; kt++) {
            #pragma unroll
            for (int np = 0; np < 4; np++) {
                uint32_t b0, b1, b2, b3;
                ldsm4(b0, b1, b2, b3,
                      yb + (brow + np * 16u) * SROW + kt * 32u + bkof);
                mma_s8(acc[0][2 * np],     afrag[0][kt], b0, b1);
                mma_s8(acc[1][2 * np],     afrag[1][kt], b0, b1);
                mma_s8(acc[0][2 * np + 1], afrag[0][kt], b2, b3);
                mma_s8(acc[1][2 * np + 1], afrag[1][kt], b2, b3);
            }
        }

        // ---- epilogue: online log2-sum-exp2 ----
        const float* ysqp = (const float*)(dsm + 4 * XTB + (g & 1) * 512);
        float2 yq[8];
        #pragma unroll
        for (int nt = 0; nt < 8; nt++)
            yq[nt] = *(const float2*)(ysqp + no + nt * 8 + 2 * tg);

        #pragma unroll
        for (int ri = 0; ri < 4; ri++) {
            const int mt = ri >> 1, hi = ri & 1;
            float2 tv[8];
            float vmax = -FLT_MAX;
            #pragma unroll
            for (int nt = 0; nt < 8; nt++) {
                tv[nt].x = fmaf((float)acc[mt][nt][2 * hi],     SFAC, -yq[nt].x);
                tv[nt].y = fmaf((float)acc[mt][nt][2 * hi + 1], SFAC, -yq[nt].y);
                vmax = fmaxf(vmax, fmaxf(tv[nt].x, tv[nt].y));
            }
            vmax = fmaxf(vmax, __shfl_xor_sync(0xffffffffu, vmax, 1));
            vmax = fmaxf(vmax, __shfl_xor_sync(0xffffffffu, vmax, 2));
            float mn = fmaxf(m_run[ri], vmax);
            float cs0 = 0.f, cs1 = 0.f;
            #pragma unroll
            for (int nt = 0; nt < 8; nt++) {
                cs0 += ex2(tv[nt].x - mn);
                cs1 += ex2(tv[nt].y - mn);
            }
            float cs = cs0 + cs1;
            cs += __shfl_xor_sync(0xffffffffu, cs, 1);
            cs += __shfl_xor_sync(0xffffffffu, cs, 2);
            s_run[ri] = fmaf(s_run[ri], ex2(m_run[ri] - mn), cs);
            m_run[ri] = mn;
        }

        // ---- unit boundary: merge n-halves, flush (m,s), reset ----
        if ((g & 3) == 3) {
            const int u = g >> 2;
            if ((lane & 3) == 0) {
                const int gq = lane >> 2;
                #pragma unroll
                for (int ri = 0; ri < 4; ri++) {
                    int rowl = mo + gq + (ri & 1) * 8 + (ri >> 1) * 16;
                    mh[wid & 1][rowl] = m_run[ri];
                    sh[wid & 1][rowl] = s_run[ri];
                }
            }
            __syncthreads();
            if (tid < BM) {
                float m0 = mh[0][tid], m1 = mh[1][tid];
                float s0 = sh[0][tid], s1 = sh[1][tid];
                float M = fmaxf(m0, m1);
                float S = fmaf(s0, ex2(m0 - M), s1 * ex2(m1 - M));
                g_m[u * BM + tid] = M;
                g_s[u * BM + tid] = S;
            }
            #pragma unroll
            for (int i = 0; i < 4; i++) { m_run[i] = -FLT_MAX; s_run[i] = 0.f; }
        }
    }
}

// ---------------------------------------------------------------------------
// Finalize: per-row merge of 16 column-unit partials; last block reduces all.
// ---------------------------------------------------------------------------
__global__ void finalize_kernel(float* __restrict__ out) {
    __shared__ float red[8];
    __shared__ bool last;
    const int tid = threadIdx.x;                 // 256
    const int row = blockIdx.x * 256 + tid;
    const int rb = row >> 7, rl = row & 127;

    float mm[16];
    float M = -FLT_MAX;
    #pragma unroll
    for (int cc = 0; cc < 16; cc++) {
        mm[cc] = g_m[(rb * 16 + cc) * BM + rl];
        M = fmaxf(M, mm[cc]);
    }
    float S = 0.f;
    #pragma unroll
    for (int cc = 0; cc < 16; cc++)
        S += g_s[(rb * 16 + cc) * BM + rl] * ex2(mm[cc] - M);

    float v = LN2 * (M + lg2(S)) - g_diag[row];
    #pragma unroll
    for (int off = 16; off; off >>= 1)
        v += __shfl_xor_sync(0xffffffffu, v, off);
    if ((tid & 31) == 0) red[tid >> 5] = v;
    __syncthreads();
    if (tid == 0) {
        float t = 0.f;
        #pragma unroll
        for (int k = 0; k < 8; k++) t += red[k];
        g_partial[blockIdx.x] = t;
        __threadfence();
        unsigned old = atomicAdd(&g_done, 1u);
        last = (old == 31u);
    }
    __syncthreads();
    if (last && tid == 0) {
        float tot = 0.f;
        #pragma unroll
        for (int k = 0; k < 32; k++)
            tot += ((volatile float*)g_partial)[k];
        out[0] = tot * (1.0f / (float)KTOT);
    }
}

// ---------------------------------------------------------------------------
extern "C" void kernel_launch(void* const* d_in, const int* in_sizes, int n_in,
                              void* d_out, int out_size) {
    const float* X = (const float*)d_in[0];  // features_nc
    const float* Y = (const float*)d_in[1];  // features_c

    const size_t dsmem = 4 * XTB + 1024;     // 2*X + 2*Y + 2*ysq = 74752 B
    cudaFuncSetAttribute(infonce_mma_kernel,
                         cudaFuncAttributeMaxDynamicSharedMemorySize, (int)dsmem);

    prep_kernel<<<(KTOT * 32) / 256, 256>>>(X, Y);
    infonce_mma_kernel<<<NCTA, 256, dsmem>>>();
    finalize_kernel<<<32, 256>>>((float*)d_out);
}

// round 6
// speedup vs baseline: 2.0789x; 2.0789x over previous
#include <cuda_runtime.h>
#include <cuda_fp16.h>
#include <float.h>
#include <stdint.h>

// loss = mean_i [ logsumexp_j t(i,j) - t(i,i) ],  t(i,j) = x_i.y_j - 0.5|y_j|^2
// K=8192, D=128. f16 mma.sync m16n8k16 (legacy tensor floor), log2-domain
// online logsumexp (per-thread, quad-merged at flush), persistent 148 CTAs.
// Diagonal exact in fp32. Single fused finalize (last-block reduction).

#define DD      128
#define KTOT    8192
#define BM      128
#define TN      128
#define YSTRIDE 272                // bytes per smem row (128 f16 + 8 pad)
#define NUNITS  1024               // (8192/128 rb) * (8192/512 cc)
#define NCTA    148
#define LOG2E   1.4426950408889634f
#define LN2     0.6931471805599453f

__device__ __half g_xb[KTOT * DD];      // x * log2e, f16
__device__ __half g_yb[KTOT * DD];      // y, f16
__device__ float  g_ysq[KTOT];          // 0.5*log2e*|y|^2
__device__ float  g_diag[KTOT];         // exact t(i,i), natural units
__device__ float  g_m[NUNITS * BM];
__device__ float  g_s[NUNITS * BM];
__device__ float  g_partial[32];
__device__ unsigned g_done;

// ---------------------------------------------------------------------------
__device__ __forceinline__ uint32_t s2u(const void* p) {
    uint32_t a;
    asm("{ .reg .u64 t; cvta.to.shared.u64 t, %1; cvt.u32.u64 %0, t; }"
        : "=r"(a) : "l"(p));
    return a;
}
__device__ __forceinline__ void cp16(uint32_t dst, const void* src) {
    asm volatile("cp.async.cg.shared.global [%0], [%1], 16;"
                 :: "r"(dst), "l"(src) : "memory");
}
__device__ __forceinline__ void ldsm4(uint32_t& r0, uint32_t& r1,
                                      uint32_t& r2, uint32_t& r3, uint32_t a) {
    asm volatile("ldmatrix.sync.aligned.m8n8.x4.shared.b16 {%0,%1,%2,%3}, [%4];"
                 : "=r"(r0), "=r"(r1), "=r"(r2), "=r"(r3) : "r"(a));
}
__device__ __forceinline__ void mma_h(uint32_t* d, const uint32_t* a,
                                      uint32_t b0, uint32_t b1) {
    asm volatile(
        "mma.sync.aligned.m16n8k16.row.col.f16.f16.f16.f16 "
        "{%0,%1}, {%2,%3,%4,%5}, {%6,%7}, {%0,%1};"
        : "+r"(d[0]), "+r"(d[1])
        : "r"(a[0]), "r"(a[1]), "r"(a[2]), "r"(a[3]), "r"(b0), "r"(b1));
}
__device__ __forceinline__ float ex2(float x) {
    float r;
    asm("ex2.approx.ftz.f32 %0, %1;" : "=f"(r) : "f"(x));
    return r;
}
__device__ __forceinline__ float lg2(float x) {
    float r;
    asm("lg2.approx.ftz.f32 %0, %1;" : "=f"(r) : "f"(x));
    return r;
}

// ---------------------------------------------------------------------------
// Prep: f16 conversion (+log2e scale on X), scaled ysq, exact fp32 diagonal.
// ---------------------------------------------------------------------------
__global__ void prep_kernel(const float* __restrict__ X, const float* __restrict__ Y) {
    if (blockIdx.x == 0 && threadIdx.x == 0) g_done = 0u;
    int gw   = (blockIdx.x * blockDim.x + threadIdx.x) >> 5;
    int lane = threadIdx.x & 31;
    if (gw >= KTOT) return;
    float4 xv = ((const float4*)(X + (size_t)gw * DD))[lane];
    float4 yv = ((const float4*)(Y + (size_t)gw * DD))[lane];
    float dot = xv.x * yv.x + xv.y * yv.y + xv.z * yv.z + xv.w * yv.w;
    float ysq = yv.x * yv.x + yv.y * yv.y + yv.z * yv.z + yv.w * yv.w;
    #pragma unroll
    for (int off = 16; off; off >>= 1) {
        dot += __shfl_xor_sync(0xffffffffu, dot, off);
        ysq += __shfl_xor_sync(0xffffffffu, ysq, off);
    }
    __half2 x01 = __float22half2_rn(make_float2(xv.x * LOG2E, xv.y * LOG2E));
    __half2 x23 = __float22half2_rn(make_float2(xv.z * LOG2E, xv.w * LOG2E));
    __half2 y01 = __float22half2_rn(make_float2(yv.x, yv.y));
    __half2 y23 = __float22half2_rn(make_float2(yv.z, yv.w));
    uint2 xp, yp;
    xp.x = *(const unsigned*)&x01;  xp.y = *(const unsigned*)&x23;
    yp.x = *(const unsigned*)&y01;  yp.y = *(const unsigned*)&y23;
    ((uint2*)(g_xb + (size_t)gw * DD))[lane] = xp;
    ((uint2*)(g_yb + (size_t)gw * DD))[lane] = yp;
    if (lane == 0) {
        g_ysq[gw]  = 0.5f * LOG2E * ysq;
        g_diag[gw] = dot - 0.5f * ysq;
    }
}

// ---------------------------------------------------------------------------
// Main: persistent CTAs, f16 HMMA + fused online logsumexp (log2 domain).
// 256 threads = 8 warps in 4(m) x 2(n); warp tile 32x64.
// Global tile g in [0,4096): rb = g>>6, col = (g&63)*128, unit = g>>2.
// ---------------------------------------------------------------------------
__global__ __launch_bounds__(256)
void infonce_mma_kernel() {
    extern __shared__ char dsm[];
    __shared__ float mh[2][BM], sh[2][BM];

    const int tid  = threadIdx.x;
    const int wid  = tid >> 5;
    const int lane = tid & 31;

    const uint32_t base = s2u(dsm);
    const uint32_t xsb[2] = {base, base + 34816u};
    const uint32_t ysb[2] = {base + 69632u, base + 104448u};
    const uint32_t yqb[2] = {base + 139264u, base + 139776u};

    const int u0 = (blockIdx.x * NUNITS) / NCTA;
    const int u1 = ((blockIdx.x + 1) * NUNITS) / NCTA;
    const int gbeg = u0 * 4, gend = u1 * 4;

    const int mo = (wid >> 1) * 32;
    const int no = (wid & 1) * 64;
    const uint32_t arow = (uint32_t)(mo + (lane & 15));
    const uint32_t acol = (uint32_t)(lane >> 4) * 16u;
    const uint32_t brow = (uint32_t)(no + ((lane >> 4) & 1) * 8 + (lane & 7));
    const uint32_t bkof = (uint32_t)((lane >> 3) & 1) * 16u;
    const int tg = lane & 3;

    // ---- prologue: X(rb0) + Y(gbeg) + ysq(gbeg), one commit group ----
    {
        const int rb0 = gbeg >> 6, col = (gbeg & 63) * TN;
        const __half* xg = g_xb + (size_t)rb0 * BM * DD;
        const __half* yg = g_yb + (size_t)col * DD;
        #pragma unroll
        for (int i = 0; i < 8; i++) {
            int c = i * 256 + tid;
            int r = c >> 4, kc = c & 15;
            cp16(xsb[0] + r * YSTRIDE + kc * 16, xg + r * DD + kc * 8);
            cp16(ysb[gbeg & 1] + r * YSTRIDE + kc * 16, yg + r * DD + kc * 8);
        }
        if (tid < 32) cp16(yqb[gbeg & 1] + tid * 16, g_ysq + col + tid * 4);
        asm volatile("cp.async.commit_group;" ::: "memory");
    }

    uint32_t afrag[2][8][4];
    int rb_prev = -1, xb = 0;
    float m_run[4], s_run[4];
    #pragma unroll
    for (int i = 0; i < 4; i++) { m_run[i] = -FLT_MAX; s_run[i] = 0.f; }

    #pragma unroll 1
    for (int g = gbeg; g < gend; g++) {
        const int rb = g >> 6;

        // ---- prefetch g+1 (Y always; X when crossing a row block) ----
        if (g + 1 < gend) {
            const int g2 = g + 1, col2 = (g2 & 63) * TN, rb2 = g2 >> 6;
            const __half* yg = g_yb + (size_t)col2 * DD;
            #pragma unroll
            for (int i = 0; i < 8; i++) {
                int c = i * 256 + tid;
                int r = c >> 4, kc = c & 15;
                cp16(ysb[g2 & 1] + r * YSTRIDE + kc * 16, yg + r * DD + kc * 8);
            }
            if (tid < 32) cp16(yqb[g2 & 1] + tid * 16, g_ysq + col2 + tid * 4);
            if (rb2 != rb) {
                const __half* xg = g_xb + (size_t)rb2 * BM * DD;
                #pragma unroll
                for (int i = 0; i < 8; i++) {
                    int c = i * 256 + tid;
                    int r = c >> 4, kc = c & 15;
                    cp16(xsb[xb ^ 1] + r * YSTRIDE + kc * 16, xg + r * DD + kc * 8);
                }
            }
            asm volatile("cp.async.commit_group;" ::: "memory");
            asm volatile("cp.async.wait_group 1;" ::: "memory");
        } else {
            asm volatile("cp.async.wait_group 0;" ::: "memory");
        }
        __syncthreads();

        // ---- (re)load A fragments on row-block change ----
        if (rb != rb_prev) {
            if (rb_prev >= 0) xb ^= 1;
            #pragma unroll
            for (int mt = 0; mt < 2; mt++)
                #pragma unroll
                for (int kt = 0; kt < 8; kt++)
                    ldsm4(afrag[mt][kt][0], afrag[mt][kt][1],
                          afrag[mt][kt][2], afrag[mt][kt][3],
                          xsb[xb] + (arow + mt * 16u) * YSTRIDE + kt * 32u + acol);
            rb_prev = rb;
        }

        // ---- GEMM tile (f16 accum) ----
        const uint32_t yb = ysb[g & 1];
        uint32_t acc[2][8][2];
        #pragma unroll
        for (int mt = 0; mt < 2; mt++)
            #pragma unroll
            for (int nt = 0; nt < 8; nt++) { acc[mt][nt][0] = 0u; acc[mt][nt][1] = 0u; }

        #pragma unroll
        for (int kt = 0; kt < 8; kt++) {
            #pragma unroll
            for (int np = 0; np < 4; np++) {
                uint32_t b0, b1, b2, b3;
                ldsm4(b0, b1, b2, b3,
                      yb + (brow + np * 16u) * YSTRIDE + kt * 32u + bkof);
                mma_h(acc[0][2 * np],     afrag[0][kt], b0, b1);
                mma_h(acc[1][2 * np],     afrag[1][kt], b0, b1);
                mma_h(acc[0][2 * np + 1], afrag[0][kt], b2, b3);
                mma_h(acc[1][2 * np + 1], afrag[1][kt], b2, b3);
            }
        }

        // ---- epilogue: per-thread online log2-sum-exp2 (no shfls here) ----
        const float* ysqp = (const float*)(dsm + 139264 + (g & 1) * 512);
        float2 yq[8];
        #pragma unroll
        for (int nt = 0; nt < 8; nt++)
            yq[nt] = *(const float2*)(ysqp + no + nt * 8 + 2 * tg);

        #pragma unroll
        for (int ri = 0; ri < 4; ri++) {
            const int mt = ri >> 1, hi = ri & 1;
            float2 tv[8];
            float vmax = -FLT_MAX;
            #pragma unroll
            for (int nt = 0; nt < 8; nt++) {
                __half2 h = *reinterpret_cast<__half2*>(&acc[mt][nt][hi]);
                float2 f = __half22float2(h);
                tv[nt].x = f.x - yq[nt].x;
                tv[nt].y = f.y - yq[nt].y;
                vmax = fmaxf(vmax, fmaxf(tv[nt].x, tv[nt].y));
            }
            float mn = fmaxf(m_run[ri], vmax);
            float cs0 = 0.f, cs1 = 0.f;
            #pragma unroll
            for (int nt = 0; nt < 8; nt++) {
                cs0 += ex2(tv[nt].x - mn);
                cs1 += ex2(tv[nt].y - mn);
            }
            s_run[ri] = fmaf(s_run[ri], ex2(m_run[ri] - mn), cs0 + cs1);
            m_run[ri] = mn;
        }

        // ---- unit boundary: quad-merge, merge n-halves, flush, reset ----
        if ((g & 3) == 3) {
            const int u = g >> 2;
            #pragma unroll
            for (int ri = 0; ri < 4; ri++) {
                #pragma unroll
                for (int off = 1; off <= 2; off <<= 1) {
                    float om = __shfl_xor_sync(0xffffffffu, m_run[ri], off);
                    float os = __shfl_xor_sync(0xffffffffu, s_run[ri], off);
                    float mn = fmaxf(m_run[ri], om);
                    s_run[ri] = fmaf(s_run[ri], ex2(m_run[ri] - mn),
                                     os * ex2(om - mn));
                    m_run[ri] = mn;
                }
            }
            if ((lane & 3) == 0) {
                const int gq = lane >> 2;
                #pragma unroll
                for (int ri = 0; ri < 4; ri++) {
                    int rowl = mo + gq + (ri & 1) * 8 + (ri >> 1) * 16;
                    mh[wid & 1][rowl] = m_run[ri];
                    sh[wid & 1][rowl] = s_run[ri];
                }
            }
            __syncthreads();
            if (tid < BM) {
                float m0 = mh[0][tid], m1 = mh[1][tid];
                float s0 = sh[0][tid], s1 = sh[1][tid];
                float M = fmaxf(m0, m1);
                float S = fmaf(s0, ex2(m0 - M), s1 * ex2(m1 - M));
                g_m[u * BM + tid] = M;
                g_s[u * BM + tid] = S;
            }
            #pragma unroll
            for (int i = 0; i < 4; i++) { m_run[i] = -FLT_MAX; s_run[i] = 0.f; }
        }
    }
}

// ---------------------------------------------------------------------------
// Finalize: per-row merge of 16 column-unit partials; last block reduces all.
// ---------------------------------------------------------------------------
__global__ void finalize_kernel(float* __restrict__ out) {
    __shared__ float red[8];
    __shared__ bool last;
    const int tid = threadIdx.x;                 // 256
    const int row = blockIdx.x * 256 + tid;
    const int rb = row >> 7, rl = row & 127;

    float mm[16];
    float M = -FLT_MAX;
    #pragma unroll
    for (int cc = 0; cc < 16; cc++) {
        mm[cc] = g_m[(rb * 16 + cc) * BM + rl];
        M = fmaxf(M, mm[cc]);
    }
    float S = 0.f;
    #pragma unroll
    for (int cc = 0; cc < 16; cc++)
        S += g_s[(rb * 16 + cc) * BM + rl] * ex2(mm[cc] - M);

    float v = LN2 * (M + lg2(S)) - g_diag[row];
    #pragma unroll
    for (int off = 16; off; off >>= 1)
        v += __shfl_xor_sync(0xffffffffu, v, off);
    if ((tid & 31) == 0) red[tid >> 5] = v;
    __syncthreads();
    if (tid == 0) {
        float t = 0.f;
        #pragma unroll
        for (int k = 0; k < 8; k++) t += red[k];
        g_partial[blockIdx.x] = t;
        __threadfence();
        unsigned old = atomicAdd(&g_done, 1u);
        last = (old == 31u);
    }
    __syncthreads();
    if (last && tid == 0) {
        float tot = 0.f;
        #pragma unroll
        for (int k = 0; k < 32; k++)
            tot += ((volatile float*)g_partial)[k];
        out[0] = tot * (1.0f / (float)KTOT);
    }
}

// ---------------------------------------------------------------------------
extern "C" void kernel_launch(void* const* d_in, const int* in_sizes, int n_in,
                              void* d_out, int out_size) {
    const float* X = (const float*)d_in[0];  // features_nc
    const float* Y = (const float*)d_in[1];  // features_c

    const size_t dsmem = 140288;  // 2*X + 2*Y + 2*ysq
    cudaFuncSetAttribute(infonce_mma_kernel,
                         cudaFuncAttributeMaxDynamicSharedMemorySize, (int)dsmem);

    prep_kernel<<<(KTOT * 32) / 256, 256>>>(X, Y);
    infonce_mma_kernel<<<NCTA, 256, dsmem>>>();
    finalize_kernel<<<32, 256>>>((float*)d_out);
}